// round 7
// baseline (speedup 1.0000x reference)
#include <cuda_runtime.h>
#include <cuda_bf16.h>
#include <cstdint>
#include <cstddef>

// ---------------------------------------------------------------------------
// Problem dims (fixed by the reference): N=8192 nodes, d0=128, d1=256, d2=256,
// qh=128, qo=1.
// Pipeline:
//   mean/var over rows of state -> x = norm(state)                (BN)
//   G1 = A @ x                  [8192,128]   (reassociated layer 1)
//   H1 = relu(G1 @ W1 + b1)     [8192,256]
//   P2 = H1 @ W2                [8192,256]
//   H2 = relu(A @ P2 + b2)      [8192,256]
//   S  = relu(H2 @ Wq1 + bq1)   [8192,128]
//   q  = S @ Wq2 + bq2          [8192,1]
// ---------------------------------------------------------------------------

#define NN      8192
#define D0      128
#define D1      256
#define D2      256
#define QH      128

// Scratch (static device globals: allocation-free rule)
__device__ float g_mean[D0];
__device__ float g_rstd[D0];
__device__ float g_X [NN * D0];
__device__ float g_G1[2 * NN * D0];     // split-K=2 halves
__device__ float g_H1[NN * D1];
__device__ float g_P2[NN * D2];
__device__ float g_G2[2 * NN * D2];     // split-K=2 halves
__device__ float g_S [NN * QH];

// ---------------- packed f32x2 helpers (sm_103a) ---------------------------
__device__ __forceinline__ unsigned long long pk2(float x, float y) {
    unsigned long long r;
    asm("mov.b64 %0, {%1, %2};" : "=l"(r) : "f"(x), "f"(y));
    return r;
}
__device__ __forceinline__ void unpk2(unsigned long long v, float& lo, float& hi) {
    asm("mov.b64 {%0, %1}, %2;" : "=f"(lo), "=f"(hi) : "l"(v));
}
__device__ __forceinline__ unsigned long long fma2(unsigned long long a,
                                                   unsigned long long b,
                                                   unsigned long long c) {
    unsigned long long d;
    asm("fma.rn.f32x2 %0, %1, %2, %3;" : "=l"(d) : "l"(a), "l"(b), "l"(c));
    return d;
}

// ---------------- BatchNorm stats: one block per feature -------------------
__global__ void bn_stats_kernel(const float* __restrict__ s, int rows, int C) {
    const int c   = blockIdx.x;
    const int tid = threadIdx.x;
    float sum = 0.f, sq = 0.f;
    for (int r = tid; r < rows; r += 256) {
        float v = s[(size_t)r * C + c];
        sum += v;
        sq   = fmaf(v, v, sq);
    }
    __shared__ float s1[256];
    __shared__ float s2[256];
    s1[tid] = sum; s2[tid] = sq;
    __syncthreads();
    #pragma unroll
    for (int o = 128; o > 0; o >>= 1) {
        if (tid < o) { s1[tid] += s1[tid + o]; s2[tid] += s2[tid + o]; }
        __syncthreads();
    }
    if (tid == 0) {
        float m   = s1[0] / rows;
        float var = s2[0] / rows - m * m;
        g_mean[c] = m;
        g_rstd[c] = rsqrtf(var + 1e-5f);
    }
}

// ---------------- normalize: x = (s-mean)*rstd*gamma + beta ----------------
__global__ void bn_apply_kernel(const float* __restrict__ s,
                                const float* __restrict__ gamma,
                                const float* __restrict__ beta,
                                float* __restrict__ X, int n4) {
    int i = blockIdx.x * blockDim.x + threadIdx.x;
    if (i >= n4) return;
    float4 v = ((const float4*)s)[i];
    int c = (i * 4) & (D0 - 1);
    v.x = (v.x - g_mean[c + 0]) * g_rstd[c + 0] * gamma[c + 0] + beta[c + 0];
    v.y = (v.y - g_mean[c + 1]) * g_rstd[c + 1] * gamma[c + 1] + beta[c + 1];
    v.z = (v.z - g_mean[c + 2]) * g_rstd[c + 2] * gamma[c + 2] + beta[c + 2];
    v.w = (v.w - g_mean[c + 3]) * g_rstd[c + 3] * gamma[c + 3] + beta[c + 3];
    ((float4*)X)[i] = v;
}

// ---------------- SGEMM: C = A[M,K] @ B[K,N], fp32, f32x2 FMA --------------
// Tile 64x128, BK=8, 128 threads, 8x8 microtile (m-paired f32x2 accumulators).
// blockIdx.z = split-K slice: computes over k in [z*kLen, (z+1)*kLen),
// writing to C + z*M*N. EPI: 0 = none, 1 = bias + relu.
#define EPN  0
#define EPBR 1

template <int EPI>
__global__ void __launch_bounds__(128, 3) sgemm64_kernel(
    const float* __restrict__ Ag, const float* __restrict__ Bg,
    float* __restrict__ Cg, const float* __restrict__ bias,
    int M, int N, int lda, int kLen)
{
    constexpr int BM = 64, BN = 128, BK = 8;
    __shared__ float As[BK][BM + 4];   // transposed, padded: conflict-free
    __shared__ float Bs[BK][BN];

    const int tid = threadIdx.x;
    const int tx  = tid & 15;          // 0..15 -> n
    const int ty  = tid >> 4;          // 0..7  -> m
    const int m0  = blockIdx.y * BM;
    const int n0  = blockIdx.x * BN;
    const int kStart = blockIdx.z * kLen;
    Cg += (size_t)blockIdx.z * M * N;

    // loader mapping
    const int arow = tid >> 1;         // 0..63
    const int akq  = (tid & 1) * 4;    // 0 or 4
    const int brow = tid >> 4;         // 0..7 (k within tile)
    const int bcol = (tid & 15) * 4;   // 0..60

    const float* Aptr = Ag + (size_t)(m0 + arow) * lda + kStart + akq;
    const float* Bptr = Bg + (size_t)(kStart + brow) * N + n0 + bcol;

    unsigned long long acc[4][8];
    #pragma unroll
    for (int i = 0; i < 4; i++)
        #pragma unroll
        for (int j = 0; j < 8; j++) acc[i][j] = 0ull;

    for (int kt = 0; kt < kLen; kt += BK) {
        float4 av  = *(const float4*)(Aptr);
        float4 bv0 = *(const float4*)(Bptr);
        float4 bv1 = *(const float4*)(Bptr + 64);
        As[akq + 0][arow] = av.x;
        As[akq + 1][arow] = av.y;
        As[akq + 2][arow] = av.z;
        As[akq + 3][arow] = av.w;
        *(float4*)&Bs[brow][bcol]      = bv0;
        *(float4*)&Bs[brow][bcol + 64] = bv1;
        __syncthreads();

        #pragma unroll
        for (int k = 0; k < BK; k++) {
            float4 a0 = *(const float4*)&As[k][ty * 8];
            float4 a1 = *(const float4*)&As[k][ty * 8 + 4];
            float4 c0 = *(const float4*)&Bs[k][tx * 8];
            float4 c1 = *(const float4*)&Bs[k][tx * 8 + 4];
            unsigned long long a2[4];
            a2[0] = pk2(a0.x, a0.y);
            a2[1] = pk2(a0.z, a0.w);
            a2[2] = pk2(a1.x, a1.y);
            a2[3] = pk2(a1.z, a1.w);
            float bv[8] = {c0.x, c0.y, c0.z, c0.w, c1.x, c1.y, c1.z, c1.w};
            #pragma unroll
            for (int j = 0; j < 8; j++) {
                unsigned long long b2 = pk2(bv[j], bv[j]);
                #pragma unroll
                for (int i = 0; i < 4; i++)
                    acc[i][j] = fma2(a2[i], b2, acc[i][j]);
            }
        }
        __syncthreads();
        Aptr += BK;
        Bptr += (size_t)BK * N;
    }

    // epilogue
    const int nbase = n0 + tx * 8;
    #pragma unroll
    for (int i = 0; i < 4; i++) {
        float r0[8], r1[8];
        #pragma unroll
        for (int j = 0; j < 8; j++) unpk2(acc[i][j], r0[j], r1[j]);
        if (EPI == EPBR) {
            #pragma unroll
            for (int j = 0; j < 8; j++) {
                float bb = bias[nbase + j];
                r0[j] = fmaxf(r0[j] + bb, 0.f);
                r1[j] = fmaxf(r1[j] + bb, 0.f);
            }
        }
        const int m = m0 + ty * 8 + 2 * i;
        float4* p0 = (float4*)(Cg + (size_t)m * N + nbase);
        float4* p1 = (float4*)(Cg + (size_t)(m + 1) * N + nbase);
        p0[0] = make_float4(r0[0], r0[1], r0[2], r0[3]);
        p0[1] = make_float4(r0[4], r0[5], r0[6], r0[7]);
        p1[0] = make_float4(r1[0], r1[1], r1[2], r1[3]);
        p1[1] = make_float4(r1[4], r1[5], r1[6], r1[7]);
    }
}

// ---------------- split-K reductions ---------------------------------------
__global__ void addbuf_kernel(float* __restrict__ a, const float* __restrict__ b, int n4) {
    int i = blockIdx.x * blockDim.x + threadIdx.x;
    if (i >= n4) return;
    float4 x = ((float4*)a)[i];
    float4 y = ((const float4*)b)[i];
    x.x += y.x; x.y += y.y; x.z += y.z; x.w += y.w;
    ((float4*)a)[i] = x;
}

__global__ void add2_bias_relu_kernel(const float* __restrict__ a,
                                      const float* __restrict__ b,
                                      const float* __restrict__ bias,
                                      float* __restrict__ out, int n4) {
    int i = blockIdx.x * blockDim.x + threadIdx.x;
    if (i >= n4) return;
    float4 x = ((const float4*)a)[i];
    float4 y = ((const float4*)b)[i];
    int c = (i * 4) & (D2 - 1);
    x.x = fmaxf(x.x + y.x + bias[c + 0], 0.f);
    x.y = fmaxf(x.y + y.y + bias[c + 1], 0.f);
    x.z = fmaxf(x.z + y.z + bias[c + 2], 0.f);
    x.w = fmaxf(x.w + y.w + bias[c + 3], 0.f);
    ((float4*)out)[i] = x;
}

// ---------------- Q head: q = S @ Wq2 + bq2 (warp per row) -----------------
__global__ void qhead_kernel(const float* __restrict__ S,
                             const float* __restrict__ Wq2,
                             const float* __restrict__ bq2,
                             float* __restrict__ q, int rows) {
    int gw   = (blockIdx.x * blockDim.x + threadIdx.x) >> 5;
    int lane = threadIdx.x & 31;
    if (gw >= rows) return;
    const float* row = S + (size_t)gw * QH;
    float sum = 0.f;
    #pragma unroll
    for (int i = 0; i < QH / 32; i++)
        sum = fmaf(row[lane + 32 * i], Wq2[lane + 32 * i], sum);
    #pragma unroll
    for (int o = 16; o > 0; o >>= 1) sum += __shfl_xor_sync(0xFFFFFFFFu, sum, o);
    if (lane == 0) q[gw] = sum + bq2[0];
}

// ---------------------------------------------------------------------------
extern "C" void kernel_launch(void* const* d_in, const int* in_sizes, int n_in,
                              void* d_out, int out_size) {
    const float* state = (const float*)d_in[0];   // [8192,128]
    const float* A     = (const float*)d_in[1];   // [8192,8192]
    const float* gamma = (const float*)d_in[2];
    const float* beta  = (const float*)d_in[3];
    const float* W1    = (const float*)d_in[4];   // [128,256]
    const float* b1    = (const float*)d_in[5];
    const float* W2    = (const float*)d_in[6];   // [256,256]
    const float* b2    = (const float*)d_in[7];
    const float* Wq1   = (const float*)d_in[8];   // [256,128]
    const float* bq1   = (const float*)d_in[9];
    const float* Wq2   = (const float*)d_in[10];  // [128,1]
    const float* bq2   = (const float*)d_in[11];
    float* q = (float*)d_out;                     // [8192]

    float *X, *G1, *H1, *P2, *G2, *S;
    cudaGetSymbolAddress((void**)&X,  g_X);
    cudaGetSymbolAddress((void**)&G1, g_G1);
    cudaGetSymbolAddress((void**)&H1, g_H1);
    cudaGetSymbolAddress((void**)&P2, g_P2);
    cudaGetSymbolAddress((void**)&G2, g_G2);
    cudaGetSymbolAddress((void**)&S,  g_S);

    // 1) BatchNorm statistics + apply
    bn_stats_kernel<<<D0, 256>>>(state, NN, D0);
    bn_apply_kernel<<<(NN * D0 / 4 + 255) / 256, 256>>>(state, gamma, beta, X, NN * D0 / 4);

    // 2) G1 = A @ X   (M=8192, N=128, K=8192; split-K=2 -> 256 CTAs)
    sgemm64_kernel<EPN><<<dim3(D0 / 128, NN / 64, 2), 128>>>(A, X, G1, nullptr,
                                                             NN, D0, NN, NN / 2);
    addbuf_kernel<<<(NN * D0 / 4 + 255) / 256, 256>>>(G1, G1 + (size_t)NN * D0, NN * D0 / 4);

    // 3) H1 = relu(G1 @ W1 + b1)  (K=128)
    sgemm64_kernel<EPBR><<<dim3(D1 / 128, NN / 64, 1), 128>>>(G1, W1, H1, b1,
                                                              NN, D1, D0, D0);

    // 4) P2 = H1 @ W2  (K=256)
    sgemm64_kernel<EPN><<<dim3(D2 / 128, NN / 64, 1), 128>>>(H1, W2, P2, nullptr,
                                                             NN, D2, D1, D1);

    // 5) G2 = A @ P2   (M=8192, N=256, K=8192; split-K=2 -> 512 CTAs)
    sgemm64_kernel<EPN><<<dim3(D2 / 128, NN / 64, 2), 128>>>(A, P2, G2, nullptr,
                                                             NN, D2, NN, NN / 2);
    // H2 = relu(G2a + G2b + b2)  (reuse H1 buffer as H2 storage -> write into g_H1? keep P2? use S? )
    add2_bias_relu_kernel<<<(NN * D2 / 4 + 255) / 256, 256>>>(G2, G2 + (size_t)NN * D2,
                                                              b2, H1, NN * D2 / 4);
    // note: H1 now holds H2 (its old contents are no longer needed)

    // 6) S = relu(H2 @ Wq1 + bq1)  (K=256, N=128)
    sgemm64_kernel<EPBR><<<dim3(QH / 128, NN / 64, 1), 128>>>(H1, Wq1, S, bq1,
                                                              NN, QH, D2, D2);

    // 7) q = S @ Wq2 + bq2
    qhead_kernel<<<(NN * 32 + 255) / 256, 256>>>(S, Wq2, bq2, q, NN);

    (void)in_sizes; (void)n_in; (void)out_size;
}

// round 9
// speedup vs baseline: 2.4521x; 2.4521x over previous
#include <cuda_runtime.h>
#include <cuda_bf16.h>
#include <cstdint>
#include <cstddef>

// ---------------------------------------------------------------------------
// N=8192 nodes, d0=128, d1=256, d2=256, qh=128, qo=1.
//   x  = batchnorm(state)                        [8192,128]
//   G1 = A @ x          (HMMA bf16 3-pass)       [8192,128]
//   H1 = relu(G1 @ W1 + b1)   (fp32 f32x2)       [8192,256]
//   P2 = H1 @ W2              (fp32 f32x2)       [8192,256]
//   G2 = A @ P2         (HMMA bf16 3-pass)       [8192,256]
//   H2 = relu(G2 + b2)
//   S  = relu(H2 @ Wq1 + bq1) (fp32 f32x2)       [8192,128]
//   q  = S @ Wq2 + bq2                           [8192,1]
// ---------------------------------------------------------------------------

#define NN      8192
#define D0      128
#define D1      256
#define D2      256
#define QH      128

// ---------------- scratch (static device globals) --------------------------
__device__ float g_mean[D0];
__device__ float g_rstd[D0];
__device__ unsigned short g_Ahi[NN * NN];        // 128 MB bf16
__device__ unsigned short g_Alo[NN * NN];        // 128 MB bf16
__device__ unsigned short g_Xt [2 * D0 * NN];    // transposed X: hi then lo
__device__ unsigned short g_Pt [2 * D2 * NN];    // transposed P2: hi then lo
__device__ float g_G1[2 * NN * D0];
__device__ float g_H1[NN * D1];
__device__ float g_P2[NN * D2];
__device__ float g_G2[2 * NN * D2];
__device__ float g_S [NN * QH];

// ---------------- PTX helpers ----------------------------------------------
__device__ __forceinline__ uint32_t smem_u32(const void* p) {
    uint32_t a;
    asm("{ .reg .u64 t; cvta.to.shared.u64 t, %1; cvt.u32.u64 %0, t; }"
        : "=r"(a) : "l"(p));
    return a;
}
__device__ __forceinline__ void cpasync16(uint32_t s, const void* g) {
    asm volatile("cp.async.cg.shared.global [%0], [%1], 16;"
                 :: "r"(s), "l"(g) : "memory");
}
__device__ __forceinline__ void ldsm4(uint32_t* r, uint32_t a) {
    asm volatile("ldmatrix.sync.aligned.m8n8.x4.shared.b16 {%0,%1,%2,%3}, [%4];"
                 : "=r"(r[0]), "=r"(r[1]), "=r"(r[2]), "=r"(r[3]) : "r"(a));
}
__device__ __forceinline__ void mma16816(float* c, const uint32_t* a,
                                         uint32_t b0, uint32_t b1) {
    asm volatile(
        "mma.sync.aligned.m16n8k16.row.col.f32.bf16.bf16.f32 "
        "{%0,%1,%2,%3}, {%4,%5,%6,%7}, {%8,%9}, {%0,%1,%2,%3};"
        : "+f"(c[0]), "+f"(c[1]), "+f"(c[2]), "+f"(c[3])
        : "r"(a[0]), "r"(a[1]), "r"(a[2]), "r"(a[3]), "r"(b0), "r"(b1));
}

// ---------------- packed f32x2 helpers --------------------------------------
__device__ __forceinline__ unsigned long long pk2(float x, float y) {
    unsigned long long r;
    asm("mov.b64 %0, {%1, %2};" : "=l"(r) : "f"(x), "f"(y));
    return r;
}
__device__ __forceinline__ void unpk2(unsigned long long v, float& lo, float& hi) {
    asm("mov.b64 {%0, %1}, %2;" : "=f"(lo), "=f"(hi) : "l"(v));
}
__device__ __forceinline__ unsigned long long fma2(unsigned long long a,
                                                   unsigned long long b,
                                                   unsigned long long c) {
    unsigned long long d;
    asm("fma.rn.f32x2 %0, %1, %2, %3;" : "=l"(d) : "l"(a), "l"(b), "l"(c));
    return d;
}

// ---------------- BatchNorm stats -------------------------------------------
__global__ void bn_stats_kernel(const float* __restrict__ s, int rows, int C) {
    const int c   = blockIdx.x;
    const int tid = threadIdx.x;
    float sum = 0.f, sq = 0.f;
    for (int r = tid; r < rows; r += 256) {
        float v = s[(size_t)r * C + c];
        sum += v;
        sq   = fmaf(v, v, sq);
    }
    __shared__ float s1[256];
    __shared__ float s2[256];
    s1[tid] = sum; s2[tid] = sq;
    __syncthreads();
    #pragma unroll
    for (int o = 128; o > 0; o >>= 1) {
        if (tid < o) { s1[tid] += s1[tid + o]; s2[tid] += s2[tid + o]; }
        __syncthreads();
    }
    if (tid == 0) {
        float m   = s1[0] / rows;
        float var = s2[0] / rows - m * m;
        g_mean[c] = m;
        g_rstd[c] = rsqrtf(var + 1e-5f);
    }
}

// ---- BN apply + transpose + bf16 split: Xt[hi|lo][d0][N] -------------------
__global__ void bn_apply_tsplit_kernel(const float* __restrict__ state,
                                       const float* __restrict__ gamma,
                                       const float* __restrict__ beta,
                                       unsigned short* __restrict__ Xt) {
    int i = blockIdx.x * 256 + threadIdx.x;
    if (i >= NN * D0) return;
    int r = i >> 7, c = i & (D0 - 1);
    float v = (state[i] - g_mean[c]) * g_rstd[c] * gamma[c] + beta[c];
    __nv_bfloat16 h = __float2bfloat16(v);
    __nv_bfloat16 l = __float2bfloat16(v - __bfloat162float(h));
    Xt[c * NN + r]            = __bfloat16_as_ushort(h);
    Xt[D0 * NN + c * NN + r]  = __bfloat16_as_ushort(l);
}

// ---- transpose + split for P2: Pt[hi|lo][d2][N] ----------------------------
__global__ void tsplit_p2_kernel(const float* __restrict__ P2,
                                 unsigned short* __restrict__ Pt) {
    int i = blockIdx.x * 256 + threadIdx.x;
    if (i >= NN * D2) return;
    int r = i >> 8, c = i & (D2 - 1);
    float v = P2[i];
    __nv_bfloat16 h = __float2bfloat16(v);
    __nv_bfloat16 l = __float2bfloat16(v - __bfloat162float(h));
    Pt[c * NN + r]            = __bfloat16_as_ushort(h);
    Pt[D2 * NN + c * NN + r]  = __bfloat16_as_ushort(l);
}

// ---- split A into hi/lo bf16 (row-major, same layout) ----------------------
__global__ void splitA_kernel(const float* __restrict__ src,
                              unsigned short* __restrict__ hi,
                              unsigned short* __restrict__ lo, int n4) {
    int i = blockIdx.x * 256 + threadIdx.x;
    if (i >= n4) return;
    float4 v = ((const float4*)src)[i];
    ushort4 h, l;
    __nv_bfloat16 b;
    b = __float2bfloat16(v.x); h.x = __bfloat16_as_ushort(b);
    l.x = __bfloat16_as_ushort(__float2bfloat16(v.x - __bfloat162float(b)));
    b = __float2bfloat16(v.y); h.y = __bfloat16_as_ushort(b);
    l.y = __bfloat16_as_ushort(__float2bfloat16(v.y - __bfloat162float(b)));
    b = __float2bfloat16(v.z); h.z = __bfloat16_as_ushort(b);
    l.z = __bfloat16_as_ushort(__float2bfloat16(v.z - __bfloat162float(b)));
    b = __float2bfloat16(v.w); h.w = __bfloat16_as_ushort(b);
    l.w = __bfloat16_as_ushort(__float2bfloat16(v.w - __bfloat162float(b)));
    ((ushort4*)hi)[i] = h;
    ((ushort4*)lo)[i] = l;
}

// ---------------------------------------------------------------------------
// HMMA bf16 3-pass GEMM: C[z] += A[m0:m0+128, k] @ Bt[n0:n0+128, k]^T
// A hi/lo row-major [NN, NN]; Bt hi at 0, lo at Nfull*NN, each [Nfull, NN]
// (K-major). BM=BN=128, BK=64, 8 warps (2x4), 3-stage cp.async pipeline.
// 3 passes (AhBh + AhBl + AlBh) accumulate into the same fp32 registers.
// ---------------------------------------------------------------------------
#define STAGES 3

__device__ __forceinline__ void load_stage(
    uint32_t sbuf, const unsigned short* __restrict__ Ah,
    const unsigned short* __restrict__ Al,
    const unsigned short* __restrict__ Bh,
    const unsigned short* __restrict__ Bl,
    int m0, int n0, int kg, int tid)
{
    constexpr int TILE = 128 * 128;   // bytes per sub-tile (128 rows x 128B)
    const int lr  = tid >> 3;         // 0..31
    const int lcb = (tid & 7) << 4;   // byte col within 128B row
    const int lce = (tid & 7) << 3;   // bf16 elem col
    #pragma unroll
    for (int it = 0; it < 4; it++) {
        int row = lr + it * 32;
        uint32_t so = (uint32_t)(row * 128) + (uint32_t)(lcb ^ ((row & 7) << 4));
        size_t ga = (size_t)(m0 + row) * NN + kg + lce;
        size_t gb = (size_t)(n0 + row) * NN + kg + lce;
        cpasync16(sbuf + so,            Ah + ga);
        cpasync16(sbuf + TILE + so,     Al + ga);
        cpasync16(sbuf + 2 * TILE + so, Bh + gb);
        cpasync16(sbuf + 3 * TILE + so, Bl + gb);
    }
    asm volatile("cp.async.commit_group;" ::: "memory");
}

__global__ void __launch_bounds__(256, 1)
hmma_gemm_kernel(const unsigned short* __restrict__ Ah,
                 const unsigned short* __restrict__ Al,
                 const unsigned short* __restrict__ Bt,
                 float* __restrict__ C, int Nfull, int kLen)
{
    constexpr int BM = 128, BN = 128, BK = 64;
    constexpr int TILE  = 128 * 128;          // 16 KB
    constexpr int STAGE = 4 * TILE;           // 64 KB (Ah, Al, Bh, Bl)
    extern __shared__ char smem[];
    const uint32_t sbase = smem_u32(smem);

    const unsigned short* Bh = Bt;
    const unsigned short* Bl = Bt + (size_t)Nfull * NN;

    const int tid    = threadIdx.x;
    const int lane   = tid & 31;
    const int wid    = tid >> 5;
    const int warp_m = wid >> 2;              // 0..1
    const int warp_n = wid & 3;               // 0..3
    const int m0     = blockIdx.y * BM;
    const int n0     = blockIdx.x * BN;
    const int kStart = blockIdx.z * kLen;
    C += (size_t)blockIdx.z * NN * Nfull;

    // ldmatrix per-lane address precompute
    // A: lanes 0..15 -> rows m0w + lane%16; lane>=16 -> k+8 (16B)
    const int rA   = lane & 15;
    const int kh16 = (lane >> 4) << 4;
    uint32_t aoff[4], axor[4];
    #pragma unroll
    for (int mb = 0; mb < 4; mb++) {
        int row  = warp_m * 64 + mb * 16 + rA;
        aoff[mb] = (uint32_t)(row * 128);
        axor[mb] = (uint32_t)((row & 7) << 4);
    }
    // B: matrix i from lanes 8i..8i+7; i0/i1 -> n rows +0..7 (k0, k0+8),
    //    i2/i3 -> n rows +8..15 (k0, k0+8)
    const int l8    = lane & 7;
    const int mi    = lane >> 3;
    const int nadd  = ((mi & 2) << 2) + l8;
    const int kadd16 = (mi & 1) << 4;
    uint32_t boff[2], bxor[2];
    #pragma unroll
    for (int np = 0; np < 2; np++) {
        int row  = warp_n * 32 + np * 16 + nadd;
        boff[np] = (uint32_t)(row * 128);
        bxor[np] = (uint32_t)((row & 7) << 4);
    }

    float acc[4][4][4];
    #pragma unroll
    for (int mb = 0; mb < 4; mb++)
        #pragma unroll
        for (int nb = 0; nb < 4; nb++)
            #pragma unroll
            for (int r = 0; r < 4; r++) acc[mb][nb][r] = 0.f;

    const int T = kLen / BK;

    // prologue: preload stages 0, 1
    load_stage(sbase + 0 * STAGE, Ah, Al, Bh, Bl, m0, n0, kStart + 0 * BK, tid);
    load_stage(sbase + 1 * STAGE, Ah, Al, Bh, Bl, m0, n0, kStart + 1 * BK, tid);

    for (int t = 0; t < T; t++) {
        if (t < T - 1) asm volatile("cp.async.wait_group 1;" ::: "memory");
        else           asm volatile("cp.async.wait_group 0;" ::: "memory");
        __syncthreads();

        const uint32_t sa_h = sbase + (t % STAGES) * STAGE;
        const uint32_t sa_l = sa_h + TILE;
        const uint32_t sb_h = sa_h + 2 * TILE;
        const uint32_t sb_l = sa_h + 3 * TILE;

        #pragma unroll
        for (int ks = 0; ks < 4; ks++) {
            const uint32_t kb = (uint32_t)(ks * 32);
            uint32_t ah[4][4], al[4][4], bh[2][4], bl[2][4];
            #pragma unroll
            for (int mb = 0; mb < 4; mb++) {
                uint32_t off = aoff[mb] + ((kb + kh16) ^ axor[mb]);
                ldsm4(ah[mb], sa_h + off);
                ldsm4(al[mb], sa_l + off);
            }
            #pragma unroll
            for (int np = 0; np < 2; np++) {
                uint32_t off = boff[np] + ((kb + kadd16) ^ bxor[np]);
                ldsm4(bh[np], sb_h + off);
                ldsm4(bl[np], sb_l + off);
            }
            #pragma unroll
            for (int mb = 0; mb < 4; mb++) {
                #pragma unroll
                for (int nb = 0; nb < 4; nb++) {
                    const int np = nb >> 1, hb = (nb & 1) * 2;
                    mma16816(acc[mb][nb], ah[mb], bh[np][hb], bh[np][hb + 1]);
                    mma16816(acc[mb][nb], ah[mb], bl[np][hb], bl[np][hb + 1]);
                    mma16816(acc[mb][nb], al[mb], bh[np][hb], bh[np][hb + 1]);
                }
            }
        }

        if (t + 2 < T)
            load_stage(sbase + ((t + 2) % STAGES) * STAGE, Ah, Al, Bh, Bl,
                       m0, n0, kStart + (t + 2) * BK, tid);
    }

    // epilogue: fp32 accumulator -> C (row-major [NN, Nfull])
    const int mrow = m0 + warp_m * 64 + (lane >> 2);
    const int ncol = n0 + warp_n * 32 + ((lane & 3) << 1);
    #pragma unroll
    for (int mb = 0; mb < 4; mb++) {
        #pragma unroll
        for (int nb = 0; nb < 4; nb++) {
            float* p0 = C + (size_t)(mrow + mb * 16) * Nfull + ncol + nb * 8;
            float* p1 = p0 + 8 * (size_t)Nfull;
            *(float2*)p0 = make_float2(acc[mb][nb][0], acc[mb][nb][1]);
            *(float2*)p1 = make_float2(acc[mb][nb][2], acc[mb][nb][3]);
        }
    }
}

// ---------------- fp32 f32x2 SGEMM (small GEMMs) ----------------------------
#define EPN  0
#define EPBR 1

template <int EPI>
__global__ void __launch_bounds__(128, 3) sgemm64_kernel(
    const float* __restrict__ Ag, const float* __restrict__ Bg,
    float* __restrict__ Cg, const float* __restrict__ bias,
    int M, int N, int lda, int kLen)
{
    constexpr int BM = 64, BN = 128, BK = 8;
    __shared__ float As[BK][BM + 4];
    __shared__ float Bs[BK][BN];

    const int tid = threadIdx.x;
    const int tx  = tid & 15;
    const int ty  = tid >> 4;
    const int m0  = blockIdx.y * BM;
    const int n0  = blockIdx.x * BN;
    const int kStart = blockIdx.z * kLen;
    Cg += (size_t)blockIdx.z * M * N;

    const int arow = tid >> 1;
    const int akq  = (tid & 1) * 4;
    const int brow = tid >> 4;
    const int bcol = (tid & 15) * 4;

    const float* Aptr = Ag + (size_t)(m0 + arow) * lda + kStart + akq;
    const float* Bptr = Bg + (size_t)(kStart + brow) * N + n0 + bcol;

    unsigned long long acc[4][8];
    #pragma unroll
    for (int i = 0; i < 4; i++)
        #pragma unroll
        for (int j = 0; j < 8; j++) acc[i][j] = 0ull;

    for (int kt = 0; kt < kLen; kt += BK) {
        float4 av  = *(const float4*)(Aptr);
        float4 bv0 = *(const float4*)(Bptr);
        float4 bv1 = *(const float4*)(Bptr + 64);
        As[akq + 0][arow] = av.x;
        As[akq + 1][arow] = av.y;
        As[akq + 2][arow] = av.z;
        As[akq + 3][arow] = av.w;
        *(float4*)&Bs[brow][bcol]      = bv0;
        *(float4*)&Bs[brow][bcol + 64] = bv1;
        __syncthreads();

        #pragma unroll
        for (int k = 0; k < BK; k++) {
            float4 a0 = *(const float4*)&As[k][ty * 8];
            float4 a1 = *(const float4*)&As[k][ty * 8 + 4];
            float4 c0 = *(const float4*)&Bs[k][tx * 8];
            float4 c1 = *(const float4*)&Bs[k][tx * 8 + 4];
            unsigned long long a2[4];
            a2[0] = pk2(a0.x, a0.y);
            a2[1] = pk2(a0.z, a0.w);
            a2[2] = pk2(a1.x, a1.y);
            a2[3] = pk2(a1.z, a1.w);
            float bv[8] = {c0.x, c0.y, c0.z, c0.w, c1.x, c1.y, c1.z, c1.w};
            #pragma unroll
            for (int j = 0; j < 8; j++) {
                unsigned long long b2 = pk2(bv[j], bv[j]);
                #pragma unroll
                for (int i = 0; i < 4; i++)
                    acc[i][j] = fma2(a2[i], b2, acc[i][j]);
            }
        }
        __syncthreads();
        Aptr += BK;
        Bptr += (size_t)BK * N;
    }

    const int nbase = n0 + tx * 8;
    #pragma unroll
    for (int i = 0; i < 4; i++) {
        float r0[8], r1[8];
        #pragma unroll
        for (int j = 0; j < 8; j++) unpk2(acc[i][j], r0[j], r1[j]);
        if (EPI == EPBR) {
            #pragma unroll
            for (int j = 0; j < 8; j++) {
                float bb = bias[nbase + j];
                r0[j] = fmaxf(r0[j] + bb, 0.f);
                r1[j] = fmaxf(r1[j] + bb, 0.f);
            }
        }
        const int m = m0 + ty * 8 + 2 * i;
        float4* p0 = (float4*)(Cg + (size_t)m * N + nbase);
        float4* p1 = (float4*)(Cg + (size_t)(m + 1) * N + nbase);
        p0[0] = make_float4(r0[0], r0[1], r0[2], r0[3]);
        p0[1] = make_float4(r0[4], r0[5], r0[6], r0[7]);
        p1[0] = make_float4(r1[0], r1[1], r1[2], r1[3]);
        p1[1] = make_float4(r1[4], r1[5], r1[6], r1[7]);
    }
}

// ---------------- split-K reductions ----------------------------------------
__global__ void addbuf_kernel(float* __restrict__ a, const float* __restrict__ b, int n4) {
    int i = blockIdx.x * blockDim.x + threadIdx.x;
    if (i >= n4) return;
    float4 x = ((float4*)a)[i];
    float4 y = ((const float4*)b)[i];
    x.x += y.x; x.y += y.y; x.z += y.z; x.w += y.w;
    ((float4*)a)[i] = x;
}

__global__ void add2_bias_relu_kernel(const float* __restrict__ a,
                                      const float* __restrict__ b,
                                      const float* __restrict__ bias,
                                      float* __restrict__ out, int n4) {
    int i = blockIdx.x * blockDim.x + threadIdx.x;
    if (i >= n4) return;
    float4 x = ((const float4*)a)[i];
    float4 y = ((const float4*)b)[i];
    int c = (i * 4) & (D2 - 1);
    x.x = fmaxf(x.x + y.x + bias[c + 0], 0.f);
    x.y = fmaxf(x.y + y.y + bias[c + 1], 0.f);
    x.z = fmaxf(x.z + y.z + bias[c + 2], 0.f);
    x.w = fmaxf(x.w + y.w + bias[c + 3], 0.f);
    ((float4*)out)[i] = x;
}

// ---------------- Q head ----------------------------------------------------
__global__ void qhead_kernel(const float* __restrict__ S,
                             const float* __restrict__ Wq2,
                             const float* __restrict__ bq2,
                             float* __restrict__ q, int rows) {
    int gw   = (blockIdx.x * blockDim.x + threadIdx.x) >> 5;
    int lane = threadIdx.x & 31;
    if (gw >= rows) return;
    const float* row = S + (size_t)gw * QH;
    float sum = 0.f;
    #pragma unroll
    for (int i = 0; i < QH / 32; i++)
        sum = fmaf(row[lane + 32 * i], Wq2[lane + 32 * i], sum);
    #pragma unroll
    for (int o = 16; o > 0; o >>= 1) sum += __shfl_xor_sync(0xFFFFFFFFu, sum, o);
    if (lane == 0) q[gw] = sum + bq2[0];
}

// ---------------------------------------------------------------------------
extern "C" void kernel_launch(void* const* d_in, const int* in_sizes, int n_in,
                              void* d_out, int out_size) {
    const float* state = (const float*)d_in[0];
    const float* A     = (const float*)d_in[1];
    const float* gamma = (const float*)d_in[2];
    const float* beta  = (const float*)d_in[3];
    const float* W1    = (const float*)d_in[4];
    const float* b1    = (const float*)d_in[5];
    const float* W2    = (const float*)d_in[6];
    const float* b2    = (const float*)d_in[7];
    const float* Wq1   = (const float*)d_in[8];
    const float* bq1   = (const float*)d_in[9];
    const float* Wq2   = (const float*)d_in[10];
    const float* bq2   = (const float*)d_in[11];
    float* q = (float*)d_out;

    unsigned short *Ahi, *Alo, *Xt, *Pt;
    float *G1, *H1, *P2, *G2, *S;
    cudaGetSymbolAddress((void**)&Ahi, g_Ahi);
    cudaGetSymbolAddress((void**)&Alo, g_Alo);
    cudaGetSymbolAddress((void**)&Xt,  g_Xt);
    cudaGetSymbolAddress((void**)&Pt,  g_Pt);
    cudaGetSymbolAddress((void**)&G1,  g_G1);
    cudaGetSymbolAddress((void**)&H1,  g_H1);
    cudaGetSymbolAddress((void**)&P2,  g_P2);
    cudaGetSymbolAddress((void**)&G2,  g_G2);
    cudaGetSymbolAddress((void**)&S,   g_S);

    // 3-stage pipeline: 3 * 64 KB = 192 KB dynamic smem
    constexpr int SMEM_HMMA = STAGES * 4 * 128 * 128;
    cudaFuncSetAttribute(hmma_gemm_kernel,
                         cudaFuncAttributeMaxDynamicSharedMemorySize, SMEM_HMMA);

    // 1) BN stats, then normalize + transpose + bf16-split X
    bn_stats_kernel<<<D0, 256>>>(state, NN, D0);
    bn_apply_tsplit_kernel<<<(NN * D0 + 255) / 256, 256>>>(state, gamma, beta, Xt);

    // 2) split A into bf16 hi/lo
    splitA_kernel<<<(NN * NN / 4 + 255) / 256, 256>>>(A, Ahi, Alo, NN * NN / 4);

    // 3) G1 = A @ X  (HMMA 3-pass, split-K=2 -> 128 CTAs)
    hmma_gemm_kernel<<<dim3(1, NN / 128, 2), 256, SMEM_HMMA>>>(Ahi, Alo, Xt, G1,
                                                               D0, NN / 2);
    addbuf_kernel<<<(NN * D0 / 4 + 255) / 256, 256>>>(G1, G1 + (size_t)NN * D0,
                                                      NN * D0 / 4);

    // 4) H1 = relu(G1 @ W1 + b1)
    sgemm64_kernel<EPBR><<<dim3(D1 / 128, NN / 64, 1), 128>>>(G1, W1, H1, b1,
                                                              NN, D1, D0, D0);

    // 5) P2 = H1 @ W2, then transpose + split
    sgemm64_kernel<EPN><<<dim3(D2 / 128, NN / 64, 1), 128>>>(H1, W2, P2, nullptr,
                                                             NN, D2, D1, D1);
    tsplit_p2_kernel<<<(NN * D2 + 255) / 256, 256>>>(P2, Pt);

    // 6) G2 = A @ P2  (HMMA 3-pass, 2 n-tiles, split-K=2 -> 256 CTAs)
    hmma_gemm_kernel<<<dim3(2, NN / 128, 2), 256, SMEM_HMMA>>>(Ahi, Alo, Pt, G2,
                                                               D2, NN / 2);
    add2_bias_relu_kernel<<<(NN * D2 / 4 + 255) / 256, 256>>>(G2, G2 + (size_t)NN * D2,
                                                              b2, H1, NN * D2 / 4);
    // H1 now holds H2

    // 7) S = relu(H2 @ Wq1 + bq1)
    sgemm64_kernel<EPBR><<<dim3(QH / 128, NN / 64, 1), 128>>>(H1, Wq1, S, bq1,
                                                              NN, QH, D2, D2);

    // 8) q = S @ Wq2 + bq2
    qhead_kernel<<<(NN * 32 + 255) / 256, 256>>>(S, Wq2, bq2, q, NN);

    (void)in_sizes; (void)n_in; (void)out_size;
}

// round 11
// speedup vs baseline: 2.5833x; 1.0535x over previous
#include <cuda_runtime.h>
#include <cuda_bf16.h>
#include <cstdint>
#include <cstddef>

// ---------------------------------------------------------------------------
// N=8192 nodes, d0=128, d1=256, d2=256, qh=128, qo=1.
//   x  = batchnorm(state)                        [8192,128]
//   G1 = A @ x          (HMMA bf16 3-pass)       [8192,128]
//   H1 = relu(G1 @ W1 + b1)   (fp32 f32x2)       [8192,256]
//   P2 = H1 @ W2              (fp32 f32x2)       [8192,256]
//   G2 = A @ P2         (HMMA bf16 3-pass)       [8192,256]
//   H2 = relu(G2 + b2)
//   S  = relu(H2 @ Wq1 + bq1) (fp32 f32x2)       [8192,128]
//   q  = S @ Wq2 + bq2                           [8192,1]
// ---------------------------------------------------------------------------

#define NN      8192
#define D0      128
#define D1      256
#define D2      256
#define QH      128

// ---------------- scratch (static device globals) --------------------------
__device__ float g_mean[D0];
__device__ float g_rstd[D0];
__device__ unsigned short g_Ahi[NN * NN];        // 128 MB bf16
__device__ unsigned short g_Alo[NN * NN];        // 128 MB bf16
__device__ unsigned short g_Xt [2 * D0 * NN];    // transposed X: hi then lo
__device__ unsigned short g_Pt [2 * D2 * NN];    // transposed P2: hi then lo
__device__ float g_G1[2 * NN * D0];              // split-K=2 halves
__device__ float g_H1[NN * D1];
__device__ float g_P2[NN * D2];
__device__ float g_G2[NN * D2];
__device__ float g_S [NN * QH];

// ---------------- PTX helpers ----------------------------------------------
__device__ __forceinline__ uint32_t smem_u32(const void* p) {
    uint32_t a;
    asm("{ .reg .u64 t; cvta.to.shared.u64 t, %1; cvt.u32.u64 %0, t; }"
        : "=r"(a) : "l"(p));
    return a;
}
__device__ __forceinline__ void cpasync16(uint32_t s, const void* g) {
    asm volatile("cp.async.cg.shared.global [%0], [%1], 16;"
                 :: "r"(s), "l"(g) : "memory");
}
__device__ __forceinline__ void ldsm4(uint32_t* r, uint32_t a) {
    asm volatile("ldmatrix.sync.aligned.m8n8.x4.shared.b16 {%0,%1,%2,%3}, [%4];"
                 : "=r"(r[0]), "=r"(r[1]), "=r"(r[2]), "=r"(r[3]) : "r"(a));
}
__device__ __forceinline__ void mma16816(float* c, const uint32_t* a,
                                         uint32_t b0, uint32_t b1) {
    asm volatile(
        "mma.sync.aligned.m16n8k16.row.col.f32.bf16.bf16.f32 "
        "{%0,%1,%2,%3}, {%4,%5,%6,%7}, {%8,%9}, {%0,%1,%2,%3};"
        : "+f"(c[0]), "+f"(c[1]), "+f"(c[2]), "+f"(c[3])
        : "r"(a[0]), "r"(a[1]), "r"(a[2]), "r"(a[3]), "r"(b0), "r"(b1));
}

// ---------------- packed f32x2 helpers --------------------------------------
__device__ __forceinline__ unsigned long long pk2(float x, float y) {
    unsigned long long r;
    asm("mov.b64 %0, {%1, %2};" : "=l"(r) : "f"(x), "f"(y));
    return r;
}
__device__ __forceinline__ void unpk2(unsigned long long v, float& lo, float& hi) {
    asm("mov.b64 {%0, %1}, %2;" : "=f"(lo), "=f"(hi) : "l"(v));
}
__device__ __forceinline__ unsigned long long fma2(unsigned long long a,
                                                   unsigned long long b,
                                                   unsigned long long c) {
    unsigned long long d;
    asm("fma.rn.f32x2 %0, %1, %2, %3;" : "=l"(d) : "l"(a), "l"(b), "l"(c));
    return d;
}

// ---------------- BatchNorm stats -------------------------------------------
__global__ void bn_stats_kernel(const float* __restrict__ s, int rows, int C) {
    const int c   = blockIdx.x;
    const int tid = threadIdx.x;
    float sum = 0.f, sq = 0.f;
    for (int r = tid; r < rows; r += 256) {
        float v = s[(size_t)r * C + c];
        sum += v;
        sq   = fmaf(v, v, sq);
    }
    __shared__ float s1[256];
    __shared__ float s2[256];
    s1[tid] = sum; s2[tid] = sq;
    __syncthreads();
    #pragma unroll
    for (int o = 128; o > 0; o >>= 1) {
        if (tid < o) { s1[tid] += s1[tid + o]; s2[tid] += s2[tid + o]; }
        __syncthreads();
    }
    if (tid == 0) {
        float m   = s1[0] / rows;
        float var = s2[0] / rows - m * m;
        g_mean[c] = m;
        g_rstd[c] = rsqrtf(var + 1e-5f);
    }
}

// ---- BN apply + tiled transpose + bf16 split: Xt[hi|lo][d0][N] -------------
// 32x32 smem tiles; coalesced loads AND stores. grid (D0/32, NN/32), 32x8 thr.
__global__ void bn_apply_tsplit_kernel(const float* __restrict__ state,
                                       const float* __restrict__ gamma,
                                       const float* __restrict__ beta,
                                       unsigned short* __restrict__ Xt) {
    __shared__ float t[32][33];
    const int c0 = blockIdx.x * 32, r0 = blockIdx.y * 32;
    const int tx = threadIdx.x, ty = threadIdx.y;
    #pragma unroll
    for (int i = 0; i < 4; i++) {
        int r = ty + i * 8;
        int c = c0 + tx;
        float v = state[(size_t)(r0 + r) * D0 + c];
        t[r][tx] = (v - g_mean[c]) * g_rstd[c] * gamma[c] + beta[c];
    }
    __syncthreads();
    #pragma unroll
    for (int i = 0; i < 4; i++) {
        int cf = ty + i * 8;                      // feature within tile
        float v = t[tx][cf];                      // node tx, feature cf
        __nv_bfloat16 h = __float2bfloat16(v);
        __nv_bfloat16 l = __float2bfloat16(v - __bfloat162float(h));
        size_t o = (size_t)(c0 + cf) * NN + r0 + tx;
        Xt[o]                     = __bfloat16_as_ushort(h);
        Xt[(size_t)D0 * NN + o]   = __bfloat16_as_ushort(l);
    }
}

// ---- tiled transpose + split for P2: Pt[hi|lo][d2][N] ----------------------
__global__ void tsplit_p2_kernel(const float* __restrict__ P2,
                                 unsigned short* __restrict__ Pt) {
    __shared__ float t[32][33];
    const int c0 = blockIdx.x * 32, r0 = blockIdx.y * 32;
    const int tx = threadIdx.x, ty = threadIdx.y;
    #pragma unroll
    for (int i = 0; i < 4; i++) {
        int r = ty + i * 8;
        t[r][tx] = P2[(size_t)(r0 + r) * D2 + c0 + tx];
    }
    __syncthreads();
    #pragma unroll
    for (int i = 0; i < 4; i++) {
        int cf = ty + i * 8;
        float v = t[tx][cf];
        __nv_bfloat16 h = __float2bfloat16(v);
        __nv_bfloat16 l = __float2bfloat16(v - __bfloat162float(h));
        size_t o = (size_t)(c0 + cf) * NN + r0 + tx;
        Pt[o]                     = __bfloat16_as_ushort(h);
        Pt[(size_t)D2 * NN + o]   = __bfloat16_as_ushort(l);
    }
}

// ---- split A into hi/lo bf16 (row-major, same layout) ----------------------
__global__ void splitA_kernel(const float* __restrict__ src,
                              unsigned short* __restrict__ hi,
                              unsigned short* __restrict__ lo, int n4) {
    int i = blockIdx.x * 256 + threadIdx.x;
    if (i >= n4) return;
    float4 v = ((const float4*)src)[i];
    ushort4 h, l;
    __nv_bfloat16 b;
    b = __float2bfloat16(v.x); h.x = __bfloat16_as_ushort(b);
    l.x = __bfloat16_as_ushort(__float2bfloat16(v.x - __bfloat162float(b)));
    b = __float2bfloat16(v.y); h.y = __bfloat16_as_ushort(b);
    l.y = __bfloat16_as_ushort(__float2bfloat16(v.y - __bfloat162float(b)));
    b = __float2bfloat16(v.z); h.z = __bfloat16_as_ushort(b);
    l.z = __bfloat16_as_ushort(__float2bfloat16(v.z - __bfloat162float(b)));
    b = __float2bfloat16(v.w); h.w = __bfloat16_as_ushort(b);
    l.w = __bfloat16_as_ushort(__float2bfloat16(v.w - __bfloat162float(b)));
    ((ushort4*)hi)[i] = h;
    ((ushort4*)lo)[i] = l;
}

// ---------------------------------------------------------------------------
// HMMA bf16 3-pass GEMM: C[z] += A[m0:m0+128, k] @ Bt[n0:n0+128, k]^T
// A hi/lo row-major [NN, NN]; Bt hi at 0, lo at Nfull*NN, each [Nfull, NN]
// (K-major). BM=BN=128, BK=64, 16 warps (4x4, warp tile 32x32), 3-stage
// cp.async pipeline. 3 passes (AhBh + AhBl + AlBh) into the same fp32 regs.
// ---------------------------------------------------------------------------
#define STAGES 3

__device__ __forceinline__ void load_stage(
    uint32_t sbuf, const unsigned short* __restrict__ Ah,
    const unsigned short* __restrict__ Al,
    const unsigned short* __restrict__ Bh,
    const unsigned short* __restrict__ Bl,
    int m0, int n0, int kg, int tid)
{
    constexpr int TILE = 128 * 128;   // bytes per sub-tile (128 rows x 128B)
    // A tiles: 2048 chunks of 16B (Ah then Al)
    #pragma unroll
    for (int it = 0; it < 4; it++) {
        int idx = tid + it * 512;
        const unsigned short* src = (idx < 1024) ? Ah : Al;
        uint32_t base = (idx < 1024) ? 0u : (uint32_t)TILE;
        int off = idx & 1023;
        int row = off >> 3, c = off & 7;
        uint32_t so = (uint32_t)(row * 128) + (uint32_t)((c * 16) ^ ((row & 7) << 4));
        cpasync16(sbuf + base + so, src + (size_t)(m0 + row) * NN + kg + c * 8);
    }
    // B tiles: 2048 chunks (Bh then Bl)
    #pragma unroll
    for (int it = 0; it < 4; it++) {
        int idx = tid + it * 512;
        const unsigned short* src = (idx < 1024) ? Bh : Bl;
        uint32_t base = 2u * TILE + ((idx < 1024) ? 0u : (uint32_t)TILE);
        int off = idx & 1023;
        int row = off >> 3, c = off & 7;
        uint32_t so = (uint32_t)(row * 128) + (uint32_t)((c * 16) ^ ((row & 7) << 4));
        cpasync16(sbuf + base + so, src + (size_t)(n0 + row) * NN + kg + c * 8);
    }
    asm volatile("cp.async.commit_group;" ::: "memory");
}

__global__ void __launch_bounds__(512, 1)
hmma_gemm_kernel(const unsigned short* __restrict__ Ah,
                 const unsigned short* __restrict__ Al,
                 const unsigned short* __restrict__ Bt,
                 float* __restrict__ C, int Nfull, int kLen)
{
    constexpr int BM = 128, BK = 64;
    constexpr int TILE  = 128 * 128;          // 16 KB
    constexpr int STAGE = 4 * TILE;           // 64 KB (Ah, Al, Bh, Bl)
    extern __shared__ char smem[];
    const uint32_t sbase = smem_u32(smem);

    const unsigned short* Bh = Bt;
    const unsigned short* Bl = Bt + (size_t)Nfull * NN;

    const int tid    = threadIdx.x;
    const int lane   = tid & 31;
    const int wid    = tid >> 5;
    const int warp_m = wid >> 2;              // 0..3
    const int warp_n = wid & 3;               // 0..3
    const int m0     = blockIdx.y * BM;
    const int n0     = blockIdx.x * 128;
    const int kStart = blockIdx.z * kLen;
    C += (size_t)blockIdx.z * NN * Nfull;

    // ldmatrix per-lane address precompute
    const int rA   = lane & 15;
    const int kh16 = (lane >> 4) << 4;
    uint32_t aoff[2], axor[2];
    #pragma unroll
    for (int mb = 0; mb < 2; mb++) {
        int row  = warp_m * 32 + mb * 16 + rA;
        aoff[mb] = (uint32_t)(row * 128);
        axor[mb] = (uint32_t)((row & 7) << 4);
    }
    const int l8     = lane & 7;
    const int mi     = lane >> 3;
    const int nadd   = ((mi & 2) << 2) + l8;
    const int kadd16 = (mi & 1) << 4;
    uint32_t boff[2], bxor[2];
    #pragma unroll
    for (int np = 0; np < 2; np++) {
        int row  = warp_n * 32 + np * 16 + nadd;
        boff[np] = (uint32_t)(row * 128);
        bxor[np] = (uint32_t)((row & 7) << 4);
    }

    float acc[2][4][4];
    #pragma unroll
    for (int mb = 0; mb < 2; mb++)
        #pragma unroll
        for (int nb = 0; nb < 4; nb++)
            #pragma unroll
            for (int r = 0; r < 4; r++) acc[mb][nb][r] = 0.f;

    const int T = kLen / BK;

    load_stage(sbase + 0 * STAGE, Ah, Al, Bh, Bl, m0, n0, kStart + 0 * BK, tid);
    load_stage(sbase + 1 * STAGE, Ah, Al, Bh, Bl, m0, n0, kStart + 1 * BK, tid);

    for (int t = 0; t < T; t++) {
        if (t < T - 1) asm volatile("cp.async.wait_group 1;" ::: "memory");
        else           asm volatile("cp.async.wait_group 0;" ::: "memory");
        __syncthreads();

        const uint32_t sa_h = sbase + (t % STAGES) * STAGE;
        const uint32_t sa_l = sa_h + TILE;
        const uint32_t sb_h = sa_h + 2 * TILE;
        const uint32_t sb_l = sa_h + 3 * TILE;

        #pragma unroll
        for (int ks = 0; ks < 4; ks++) {
            const uint32_t kb = (uint32_t)(ks * 32);
            uint32_t ah[2][4], al[2][4], bh[2][4], bl[2][4];
            #pragma unroll
            for (int mb = 0; mb < 2; mb++) {
                uint32_t off = aoff[mb] + ((kb + kh16) ^ axor[mb]);
                ldsm4(ah[mb], sa_h + off);
                ldsm4(al[mb], sa_l + off);
            }
            #pragma unroll
            for (int np = 0; np < 2; np++) {
                uint32_t off = boff[np] + ((kb + kadd16) ^ bxor[np]);
                ldsm4(bh[np], sb_h + off);
                ldsm4(bl[np], sb_l + off);
            }
            #pragma unroll
            for (int mb = 0; mb < 2; mb++) {
                #pragma unroll
                for (int nb = 0; nb < 4; nb++) {
                    const int np = nb >> 1, hb = (nb & 1) * 2;
                    mma16816(acc[mb][nb], ah[mb], bh[np][hb], bh[np][hb + 1]);
                    mma16816(acc[mb][nb], ah[mb], bl[np][hb], bl[np][hb + 1]);
                    mma16816(acc[mb][nb], al[mb], bh[np][hb], bh[np][hb + 1]);
                }
            }
        }

        if (t + 2 < T)
            load_stage(sbase + ((t + 2) % STAGES) * STAGE, Ah, Al, Bh, Bl,
                       m0, n0, kStart + (t + 2) * BK, tid);
    }

    // epilogue: fp32 accumulator -> C (row-major [NN, Nfull])
    const int mrow = m0 + warp_m * 32 + (lane >> 2);
    const int ncol = n0 + warp_n * 32 + ((lane & 3) << 1);
    #pragma unroll
    for (int mb = 0; mb < 2; mb++) {
        #pragma unroll
        for (int nb = 0; nb < 4; nb++) {
            float* p0 = C + (size_t)(mrow + mb * 16) * Nfull + ncol + nb * 8;
            float* p1 = p0 + 8 * (size_t)Nfull;
            *(float2*)p0 = make_float2(acc[mb][nb][0], acc[mb][nb][1]);
            *(float2*)p1 = make_float2(acc[mb][nb][2], acc[mb][nb][3]);
        }
    }
}

// ---------------- fp32 f32x2 SGEMM (small GEMMs) ----------------------------
#define EPN  0
#define EPBR 1

template <int EPI>
__global__ void __launch_bounds__(128, 3) sgemm64_kernel(
    const float* __restrict__ Ag, const float* __restrict__ Bg,
    float* __restrict__ Cg, const float* __restrict__ bias,
    int M, int N, int lda, int kLen)
{
    constexpr int BM = 64, BN = 128, BK = 8;
    __shared__ float As[BK][BM + 4];
    __shared__ float Bs[BK][BN];

    const int tid = threadIdx.x;
    const int tx  = tid & 15;
    const int ty  = tid >> 4;
    const int m0  = blockIdx.y * BM;
    const int n0  = blockIdx.x * BN;
    const int kStart = blockIdx.z * kLen;
    Cg += (size_t)blockIdx.z * M * N;

    const int arow = tid >> 1;
    const int akq  = (tid & 1) * 4;
    const int brow = tid >> 4;
    const int bcol = (tid & 15) * 4;

    const float* Aptr = Ag + (size_t)(m0 + arow) * lda + kStart + akq;
    const float* Bptr = Bg + (size_t)(kStart + brow) * N + n0 + bcol;

    unsigned long long acc[4][8];
    #pragma unroll
    for (int i = 0; i < 4; i++)
        #pragma unroll
        for (int j = 0; j < 8; j++) acc[i][j] = 0ull;

    for (int kt = 0; kt < kLen; kt += BK) {
        float4 av  = *(const float4*)(Aptr);
        float4 bv0 = *(const float4*)(Bptr);
        float4 bv1 = *(const float4*)(Bptr + 64);
        As[akq + 0][arow] = av.x;
        As[akq + 1][arow] = av.y;
        As[akq + 2][arow] = av.z;
        As[akq + 3][arow] = av.w;
        *(float4*)&Bs[brow][bcol]      = bv0;
        *(float4*)&Bs[brow][bcol + 64] = bv1;
        __syncthreads();

        #pragma unroll
        for (int k = 0; k < BK; k++) {
            float4 a0 = *(const float4*)&As[k][ty * 8];
            float4 a1 = *(const float4*)&As[k][ty * 8 + 4];
            float4 c0 = *(const float4*)&Bs[k][tx * 8];
            float4 c1 = *(const float4*)&Bs[k][tx * 8 + 4];
            unsigned long long a2[4];
            a2[0] = pk2(a0.x, a0.y);
            a2[1] = pk2(a0.z, a0.w);
            a2[2] = pk2(a1.x, a1.y);
            a2[3] = pk2(a1.z, a1.w);
            float bv[8] = {c0.x, c0.y, c0.z, c0.w, c1.x, c1.y, c1.z, c1.w};
            #pragma unroll
            for (int j = 0; j < 8; j++) {
                unsigned long long b2 = pk2(bv[j], bv[j]);
                #pragma unroll
                for (int i = 0; i < 4; i++)
                    acc[i][j] = fma2(a2[i], b2, acc[i][j]);
            }
        }
        __syncthreads();
        Aptr += BK;
        Bptr += (size_t)BK * N;
    }

    const int nbase = n0 + tx * 8;
    #pragma unroll
    for (int i = 0; i < 4; i++) {
        float r0[8], r1[8];
        #pragma unroll
        for (int j = 0; j < 8; j++) unpk2(acc[i][j], r0[j], r1[j]);
        if (EPI == EPBR) {
            #pragma unroll
            for (int j = 0; j < 8; j++) {
                float bb = bias[nbase + j];
                r0[j] = fmaxf(r0[j] + bb, 0.f);
                r1[j] = fmaxf(r1[j] + bb, 0.f);
            }
        }
        const int m = m0 + ty * 8 + 2 * i;
        float4* p0 = (float4*)(Cg + (size_t)m * N + nbase);
        float4* p1 = (float4*)(Cg + (size_t)(m + 1) * N + nbase);
        p0[0] = make_float4(r0[0], r0[1], r0[2], r0[3]);
        p0[1] = make_float4(r0[4], r0[5], r0[6], r0[7]);
        p1[0] = make_float4(r1[0], r1[1], r1[2], r1[3]);
        p1[1] = make_float4(r1[4], r1[5], r1[6], r1[7]);
    }
}

// ---------------- reductions / epilogues ------------------------------------
__global__ void addbuf_kernel(float* __restrict__ a, const float* __restrict__ b, int n4) {
    int i = blockIdx.x * blockDim.x + threadIdx.x;
    if (i >= n4) return;
    float4 x = ((float4*)a)[i];
    float4 y = ((const float4*)b)[i];
    x.x += y.x; x.y += y.y; x.z += y.z; x.w += y.w;
    ((float4*)a)[i] = x;
}

__global__ void bias_relu_kernel(const float* __restrict__ a,
                                 const float* __restrict__ bias,
                                 float* __restrict__ out, int n4) {
    int i = blockIdx.x * blockDim.x + threadIdx.x;
    if (i >= n4) return;
    float4 x = ((const float4*)a)[i];
    int c = (i * 4) & (D2 - 1);
    x.x = fmaxf(x.x + bias[c + 0], 0.f);
    x.y = fmaxf(x.y + bias[c + 1], 0.f);
    x.z = fmaxf(x.z + bias[c + 2], 0.f);
    x.w = fmaxf(x.w + bias[c + 3], 0.f);
    ((float4*)out)[i] = x;
}

// ---------------- Q head ----------------------------------------------------
__global__ void qhead_kernel(const float* __restrict__ S,
                             const float* __restrict__ Wq2,
                             const float* __restrict__ bq2,
                             float* __restrict__ q, int rows) {
    int gw   = (blockIdx.x * blockDim.x + threadIdx.x) >> 5;
    int lane = threadIdx.x & 31;
    if (gw >= rows) return;
    const float* row = S + (size_t)gw * QH;
    float sum = 0.f;
    #pragma unroll
    for (int i = 0; i < QH / 32; i++)
        sum = fmaf(row[lane + 32 * i], Wq2[lane + 32 * i], sum);
    #pragma unroll
    for (int o = 16; o > 0; o >>= 1) sum += __shfl_xor_sync(0xFFFFFFFFu, sum, o);
    if (lane == 0) q[gw] = sum + bq2[0];
}

// ---------------------------------------------------------------------------
extern "C" void kernel_launch(void* const* d_in, const int* in_sizes, int n_in,
                              void* d_out, int out_size) {
    const float* state = (const float*)d_in[0];
    const float* A     = (const float*)d_in[1];
    const float* gamma = (const float*)d_in[2];
    const float* beta  = (const float*)d_in[3];
    const float* W1    = (const float*)d_in[4];
    const float* b1    = (const float*)d_in[5];
    const float* W2    = (const float*)d_in[6];
    const float* b2    = (const float*)d_in[7];
    const float* Wq1   = (const float*)d_in[8];
    const float* bq1   = (const float*)d_in[9];
    const float* Wq2   = (const float*)d_in[10];
    const float* bq2   = (const float*)d_in[11];
    float* q = (float*)d_out;

    unsigned short *Ahi, *Alo, *Xt, *Pt;
    float *G1, *H1, *P2, *G2, *S;
    cudaGetSymbolAddress((void**)&Ahi, g_Ahi);
    cudaGetSymbolAddress((void**)&Alo, g_Alo);
    cudaGetSymbolAddress((void**)&Xt,  g_Xt);
    cudaGetSymbolAddress((void**)&Pt,  g_Pt);
    cudaGetSymbolAddress((void**)&G1,  g_G1);
    cudaGetSymbolAddress((void**)&H1,  g_H1);
    cudaGetSymbolAddress((void**)&P2,  g_P2);
    cudaGetSymbolAddress((void**)&G2,  g_G2);
    cudaGetSymbolAddress((void**)&S,   g_S);

    // 3-stage pipeline: 3 * 64 KB = 192 KB dynamic smem
    constexpr int SMEM_HMMA = STAGES * 4 * 128 * 128;
    cudaFuncSetAttribute(hmma_gemm_kernel,
                         cudaFuncAttributeMaxDynamicSharedMemorySize, SMEM_HMMA);

    // 1) BN stats, then normalize + tiled transpose + bf16-split X
    bn_stats_kernel<<<D0, 256>>>(state, NN, D0);
    bn_apply_tsplit_kernel<<<dim3(D0 / 32, NN / 32), dim3(32, 8)>>>(state, gamma,
                                                                    beta, Xt);

    // 2) split A into bf16 hi/lo
    splitA_kernel<<<(NN * NN / 4 + 255) / 256, 256>>>(A, Ahi, Alo, NN * NN / 4);

    // 3) G1 = A @ X  (HMMA 3-pass, split-K=2 -> 128 CTAs)
    hmma_gemm_kernel<<<dim3(1, NN / 128, 2), 512, SMEM_HMMA>>>(Ahi, Alo, Xt, G1,
                                                               D0, NN / 2);
    addbuf_kernel<<<(NN * D0 / 4 + 255) / 256, 256>>>(G1, G1 + (size_t)NN * D0,
                                                      NN * D0 / 4);

    // 4) H1 = relu(G1 @ W1 + b1)
    sgemm64_kernel<EPBR><<<dim3(D1 / 128, NN / 64, 1), 128>>>(G1, W1, H1, b1,
                                                              NN, D1, D0, D0);

    // 5) P2 = H1 @ W2, then tiled transpose + split
    sgemm64_kernel<EPN><<<dim3(D2 / 128, NN / 64, 1), 128>>>(H1, W2, P2, nullptr,
                                                             NN, D2, D1, D1);
    tsplit_p2_kernel<<<dim3(D2 / 32, NN / 32), dim3(32, 8)>>>(P2, Pt);

    // 6) G2 = A @ P2  (HMMA 3-pass, 2 n-tiles, full K -> 128 CTAs, one wave)
    hmma_gemm_kernel<<<dim3(2, NN / 128, 1), 512, SMEM_HMMA>>>(Ahi, Alo, Pt, G2,
                                                               D2, NN);
    bias_relu_kernel<<<(NN * D2 / 4 + 255) / 256, 256>>>(G2, b2, H1, NN * D2 / 4);
    // H1 now holds H2

    // 7) S = relu(H2 @ Wq1 + bq1)
    sgemm64_kernel<EPBR><<<dim3(QH / 128, NN / 64, 1), 128>>>(H1, Wq1, S, bq1,
                                                              NN, QH, D2, D2);

    // 8) q = S @ Wq2 + bq2
    qhead_kernel<<<(NN * 32 + 255) / 256, 256>>>(S, Wq2, bq2, q, NN);

    (void)in_sizes; (void)n_in; (void)out_size;
}

// round 13
// speedup vs baseline: 2.7024x; 1.0461x over previous
#include <cuda_runtime.h>
#include <cuda_bf16.h>
#include <cstdint>
#include <cstddef>

// ---------------------------------------------------------------------------
// N=8192 nodes, d0=128, d1=256, d2=256, qh=128, qo=1.
//   x  = batchnorm(state)                        [8192,128]
//   G1 = A @ x          (HMMA bf16 3-pass)       [8192,128]
//   H1 = relu(G1 @ W1 + b1)   (fp32 f32x2)       [8192,256]
//   P2 = H1 @ W2              (fp32 f32x2)       [8192,256]
//   G2 = A @ P2         (HMMA bf16 3-pass)       [8192,256]
//   H2 = relu(G2 + b2)
//   S  = relu(H2 @ Wq1 + bq1) (fp32 f32x2)       [8192,128]
//   q  = S @ Wq2 + bq2                           [8192,1]
// ---------------------------------------------------------------------------

#define NN      8192
#define D0      128
#define D1      256
#define D2      256
#define QH      128

// ---------------- scratch (static device globals) --------------------------
__device__ float g_mean[D0];
__device__ float g_rstd[D0];
__device__ unsigned short g_Ahi[NN * NN];        // 128 MB bf16
__device__ unsigned short g_Alo[NN * NN];        // 128 MB bf16
__device__ unsigned short g_Xt [2 * D0 * NN];    // transposed X: hi then lo
__device__ unsigned short g_Pt [2 * D2 * NN];    // transposed P2: hi then lo
__device__ float g_G1[4 * NN * D0];              // split-K=4 slices
__device__ float g_H1[NN * D1];
__device__ float g_P2[NN * D2];
__device__ float g_G2[2 * NN * D2];              // split-K=2 slices
__device__ float g_S [NN * QH];

// ---------------- PTX helpers ----------------------------------------------
__device__ __forceinline__ uint32_t smem_u32(const void* p) {
    uint32_t a;
    asm("{ .reg .u64 t; cvta.to.shared.u64 t, %1; cvt.u32.u64 %0, t; }"
        : "=r"(a) : "l"(p));
    return a;
}
__device__ __forceinline__ void cpasync16(uint32_t s, const void* g) {
    asm volatile("cp.async.cg.shared.global [%0], [%1], 16;"
                 :: "r"(s), "l"(g) : "memory");
}
__device__ __forceinline__ void ldsm4(uint32_t* r, uint32_t a) {
    asm volatile("ldmatrix.sync.aligned.m8n8.x4.shared.b16 {%0,%1,%2,%3}, [%4];"
                 : "=r"(r[0]), "=r"(r[1]), "=r"(r[2]), "=r"(r[3]) : "r"(a));
}
__device__ __forceinline__ void mma16816(float* c, const uint32_t* a,
                                         uint32_t b0, uint32_t b1) {
    asm volatile(
        "mma.sync.aligned.m16n8k16.row.col.f32.bf16.bf16.f32 "
        "{%0,%1,%2,%3}, {%4,%5,%6,%7}, {%8,%9}, {%0,%1,%2,%3};"
        : "+f"(c[0]), "+f"(c[1]), "+f"(c[2]), "+f"(c[3])
        : "r"(a[0]), "r"(a[1]), "r"(a[2]), "r"(a[3]), "r"(b0), "r"(b1));
}

// ---------------- packed f32x2 helpers --------------------------------------
__device__ __forceinline__ unsigned long long pk2(float x, float y) {
    unsigned long long r;
    asm("mov.b64 %0, {%1, %2};" : "=l"(r) : "f"(x), "f"(y));
    return r;
}
__device__ __forceinline__ void unpk2(unsigned long long v, float& lo, float& hi) {
    asm("mov.b64 {%0, %1}, %2;" : "=f"(lo), "=f"(hi) : "l"(v));
}
__device__ __forceinline__ unsigned long long fma2(unsigned long long a,
                                                   unsigned long long b,
                                                   unsigned long long c) {
    unsigned long long d;
    asm("fma.rn.f32x2 %0, %1, %2, %3;" : "=l"(d) : "l"(a), "l"(b), "l"(c));
    return d;
}

// ---------------- BatchNorm stats -------------------------------------------
__global__ void bn_stats_kernel(const float* __restrict__ s, int rows, int C) {
    const int c   = blockIdx.x;
    const int tid = threadIdx.x;
    float sum = 0.f, sq = 0.f;
    for (int r = tid; r < rows; r += 256) {
        float v = s[(size_t)r * C + c];
        sum += v;
        sq   = fmaf(v, v, sq);
    }
    __shared__ float s1[256];
    __shared__ float s2[256];
    s1[tid] = sum; s2[tid] = sq;
    __syncthreads();
    #pragma unroll
    for (int o = 128; o > 0; o >>= 1) {
        if (tid < o) { s1[tid] += s1[tid + o]; s2[tid] += s2[tid + o]; }
        __syncthreads();
    }
    if (tid == 0) {
        float m   = s1[0] / rows;
        float var = s2[0] / rows - m * m;
        g_mean[c] = m;
        g_rstd[c] = rsqrtf(var + 1e-5f);
    }
}

// ---- BN apply + tiled transpose + bf16 split: Xt[hi|lo][d0][N] -------------
__global__ void bn_apply_tsplit_kernel(const float* __restrict__ state,
                                       const float* __restrict__ gamma,
                                       const float* __restrict__ beta,
                                       unsigned short* __restrict__ Xt) {
    __shared__ float t[32][33];
    const int c0 = blockIdx.x * 32, r0 = blockIdx.y * 32;
    const int tx = threadIdx.x, ty = threadIdx.y;
    #pragma unroll
    for (int i = 0; i < 4; i++) {
        int r = ty + i * 8;
        int c = c0 + tx;
        float v = state[(size_t)(r0 + r) * D0 + c];
        t[r][tx] = (v - g_mean[c]) * g_rstd[c] * gamma[c] + beta[c];
    }
    __syncthreads();
    #pragma unroll
    for (int i = 0; i < 4; i++) {
        int cf = ty + i * 8;
        float v = t[tx][cf];
        __nv_bfloat16 h = __float2bfloat16(v);
        __nv_bfloat16 l = __float2bfloat16(v - __bfloat162float(h));
        size_t o = (size_t)(c0 + cf) * NN + r0 + tx;
        Xt[o]                     = __bfloat16_as_ushort(h);
        Xt[(size_t)D0 * NN + o]   = __bfloat16_as_ushort(l);
    }
}

// ---- tiled transpose + split for P2: Pt[hi|lo][d2][N] ----------------------
__global__ void tsplit_p2_kernel(const float* __restrict__ P2,
                                 unsigned short* __restrict__ Pt) {
    __shared__ float t[32][33];
    const int c0 = blockIdx.x * 32, r0 = blockIdx.y * 32;
    const int tx = threadIdx.x, ty = threadIdx.y;
    #pragma unroll
    for (int i = 0; i < 4; i++) {
        int r = ty + i * 8;
        t[r][tx] = P2[(size_t)(r0 + r) * D2 + c0 + tx];
    }
    __syncthreads();
    #pragma unroll
    for (int i = 0; i < 4; i++) {
        int cf = ty + i * 8;
        float v = t[tx][cf];
        __nv_bfloat16 h = __float2bfloat16(v);
        __nv_bfloat16 l = __float2bfloat16(v - __bfloat162float(h));
        size_t o = (size_t)(c0 + cf) * NN + r0 + tx;
        Pt[o]                     = __bfloat16_as_ushort(h);
        Pt[(size_t)D2 * NN + o]   = __bfloat16_as_ushort(l);
    }
}

// ---- split A into hi/lo bf16 (row-major, same layout) ----------------------
__global__ void splitA_kernel(const float* __restrict__ src,
                              unsigned short* __restrict__ hi,
                              unsigned short* __restrict__ lo, int n4) {
    int i = blockIdx.x * 256 + threadIdx.x;
    if (i >= n4) return;
    float4 v = ((const float4*)src)[i];
    ushort4 h, l;
    __nv_bfloat16 b;
    b = __float2bfloat16(v.x); h.x = __bfloat16_as_ushort(b);
    l.x = __bfloat16_as_ushort(__float2bfloat16(v.x - __bfloat162float(b)));
    b = __float2bfloat16(v.y); h.y = __bfloat16_as_ushort(b);
    l.y = __bfloat16_as_ushort(__float2bfloat16(v.y - __bfloat162float(b)));
    b = __float2bfloat16(v.z); h.z = __bfloat16_as_ushort(b);
    l.z = __bfloat16_as_ushort(__float2bfloat16(v.z - __bfloat162float(b)));
    b = __float2bfloat16(v.w); h.w = __bfloat16_as_ushort(b);
    l.w = __bfloat16_as_ushort(__float2bfloat16(v.w - __bfloat162float(b)));
    ((ushort4*)hi)[i] = h;
    ((ushort4*)lo)[i] = l;
}

// ---------------------------------------------------------------------------
// HMMA bf16 3-pass GEMM: C[z] += A[m0:m0+256, k] @ Bt[n0:n0+128, k]^T
// A hi/lo row-major [NN, NN]; Bt hi at 0, lo at Nfull*NN, each [Nfull, NN]
// (K-major). CTA tile 256x128, BK=64, 8 warps (4m x 2n, warp tile 64x64),
// 2-stage cp.async pipeline (96 KB/stage). 3 passes into the same fp32 regs.
// ---------------------------------------------------------------------------
constexpr int TILE_A = 256 * 128;          // 32 KB per A sub-tile
constexpr int TILE_B = 128 * 128;          // 16 KB per B sub-tile
constexpr int STAGE_BYTES = 2 * TILE_A + 2 * TILE_B;   // 96 KB

__device__ __forceinline__ void load_stage(
    uint32_t sbuf, const unsigned short* __restrict__ Ah,
    const unsigned short* __restrict__ Al,
    const unsigned short* __restrict__ Bh,
    const unsigned short* __restrict__ Bl,
    int m0, int n0, int kg, int tid)
{
    // A: 2048 chunks of 16B per sub-tile (256 rows x 8)
    #pragma unroll
    for (int it = 0; it < 8; it++) {
        int idx = tid + it * 256;
        int row = idx >> 3, c = idx & 7;
        uint32_t so = (uint32_t)(row * 128) + (uint32_t)((c * 16) ^ ((row & 7) << 4));
        size_t g = (size_t)(m0 + row) * NN + kg + c * 8;
        cpasync16(sbuf + so,          Ah + g);
        cpasync16(sbuf + TILE_A + so, Al + g);
    }
    // B: 1024 chunks per sub-tile (128 rows x 8)
    #pragma unroll
    for (int it = 0; it < 4; it++) {
        int idx = tid + it * 256;
        int row = idx >> 3, c = idx & 7;
        uint32_t so = (uint32_t)(row * 128) + (uint32_t)((c * 16) ^ ((row & 7) << 4));
        size_t g = (size_t)(n0 + row) * NN + kg + c * 8;
        cpasync16(sbuf + 2 * TILE_A + so,          Bh + g);
        cpasync16(sbuf + 2 * TILE_A + TILE_B + so, Bl + g);
    }
    asm volatile("cp.async.commit_group;" ::: "memory");
}

__global__ void __launch_bounds__(256, 1)
hmma_gemm_kernel(const unsigned short* __restrict__ Ah,
                 const unsigned short* __restrict__ Al,
                 const unsigned short* __restrict__ Bt,
                 float* __restrict__ C, int Nfull, int kLen)
{
    extern __shared__ char smem[];
    const uint32_t sbase = smem_u32(smem);

    const unsigned short* Bh = Bt;
    const unsigned short* Bl = Bt + (size_t)Nfull * NN;

    const int tid    = threadIdx.x;
    const int lane   = tid & 31;
    const int wid    = tid >> 5;
    const int warp_m = wid >> 1;              // 0..3  (m64 rows)
    const int warp_n = wid & 1;               // 0..1  (n64 cols)
    const int m0     = blockIdx.y * 256;
    const int n0     = blockIdx.x * 128;
    const int kStart = blockIdx.z * kLen;
    C += (size_t)blockIdx.z * NN * Nfull;

    // ldmatrix per-lane address precompute
    const int rA   = lane & 15;
    const int kh16 = (lane >> 4) << 4;        // byte offset within 32B k-pair
    uint32_t aoff[4], axor[4];
    #pragma unroll
    for (int mb = 0; mb < 4; mb++) {
        int row  = warp_m * 64 + mb * 16 + rA;
        aoff[mb] = (uint32_t)(row * 128);
        axor[mb] = (uint32_t)((row & 7) << 4);
    }
    const int l8     = lane & 7;
    const int mi     = lane >> 3;
    const int nadd   = ((mi & 2) << 2) + l8;
    const int kadd16 = (mi & 1) << 4;
    uint32_t boff[4], bxor[4];
    #pragma unroll
    for (int np = 0; np < 4; np++) {
        int row  = warp_n * 64 + np * 16 + nadd;
        boff[np] = (uint32_t)(row * 128);
        bxor[np] = (uint32_t)((row & 7) << 4);
    }

    float acc[4][8][4];
    #pragma unroll
    for (int mb = 0; mb < 4; mb++)
        #pragma unroll
        for (int nb = 0; nb < 8; nb++)
            #pragma unroll
            for (int r = 0; r < 4; r++) acc[mb][nb][r] = 0.f;

    const int T = kLen / 64;

    load_stage(sbase, Ah, Al, Bh, Bl, m0, n0, kStart, tid);

    for (int t = 0; t < T; t++) {
        if (t + 1 < T) {
            load_stage(sbase + ((t + 1) & 1) * STAGE_BYTES, Ah, Al, Bh, Bl,
                       m0, n0, kStart + (t + 1) * 64, tid);
            asm volatile("cp.async.wait_group 1;" ::: "memory");
        } else {
            asm volatile("cp.async.wait_group 0;" ::: "memory");
        }
        __syncthreads();

        const uint32_t sa_h = sbase + (t & 1) * STAGE_BYTES;
        const uint32_t sa_l = sa_h + TILE_A;
        const uint32_t sb_h = sa_h + 2 * TILE_A;
        const uint32_t sb_l = sb_h + TILE_B;

        #pragma unroll
        for (int ks = 0; ks < 4; ks++) {
            const uint32_t kb = (uint32_t)(ks * 32);
            uint32_t ah[4][4], al[4][4];
            #pragma unroll
            for (int mb = 0; mb < 4; mb++) {
                uint32_t off = aoff[mb] + ((kb + kh16) ^ axor[mb]);
                ldsm4(ah[mb], sa_h + off);
                ldsm4(al[mb], sa_l + off);
            }
            #pragma unroll
            for (int np = 0; np < 4; np++) {
                uint32_t bh[4], bl[4];
                uint32_t off = boff[np] + ((kb + kadd16) ^ bxor[np]);
                ldsm4(bh, sb_h + off);
                ldsm4(bl, sb_l + off);
                #pragma unroll
                for (int mb = 0; mb < 4; mb++) {
                    mma16816(acc[mb][np * 2 + 0], ah[mb], bh[0], bh[1]);
                    mma16816(acc[mb][np * 2 + 0], ah[mb], bl[0], bl[1]);
                    mma16816(acc[mb][np * 2 + 0], al[mb], bh[0], bh[1]);
                    mma16816(acc[mb][np * 2 + 1], ah[mb], bh[2], bh[3]);
                    mma16816(acc[mb][np * 2 + 1], ah[mb], bl[2], bl[3]);
                    mma16816(acc[mb][np * 2 + 1], al[mb], bh[2], bh[3]);
                }
            }
        }
        __syncthreads();
    }

    // epilogue: fp32 accumulator -> C (row-major [NN, Nfull])
    const int mrow = m0 + warp_m * 64 + (lane >> 2);
    const int ncol = n0 + warp_n * 64 + ((lane & 3) << 1);
    #pragma unroll
    for (int mb = 0; mb < 4; mb++) {
        #pragma unroll
        for (int nb = 0; nb < 8; nb++) {
            float* p0 = C + (size_t)(mrow + mb * 16) * Nfull + ncol + nb * 8;
            float* p1 = p0 + 8 * (size_t)Nfull;
            *(float2*)p0 = make_float2(acc[mb][nb][0], acc[mb][nb][1]);
            *(float2*)p1 = make_float2(acc[mb][nb][2], acc[mb][nb][3]);
        }
    }
}

// ---------------- fp32 f32x2 SGEMM (small GEMMs) ----------------------------
#define EPN  0
#define EPBR 1

template <int EPI>
__global__ void __launch_bounds__(128, 3) sgemm64_kernel(
    const float* __restrict__ Ag, const float* __restrict__ Bg,
    float* __restrict__ Cg, const float* __restrict__ bias,
    int M, int N, int lda, int kLen)
{
    constexpr int BM = 64, BN = 128, BK = 8;
    __shared__ float As[BK][BM + 4];
    __shared__ float Bs[BK][BN];

    const int tid = threadIdx.x;
    const int tx  = tid & 15;
    const int ty  = tid >> 4;
    const int m0  = blockIdx.y * BM;
    const int n0  = blockIdx.x * BN;
    Cg += 0;

    const int arow = tid >> 1;
    const int akq  = (tid & 1) * 4;
    const int brow = tid >> 4;
    const int bcol = (tid & 15) * 4;

    const float* Aptr = Ag + (size_t)(m0 + arow) * lda + akq;
    const float* Bptr = Bg + (size_t)brow * N + n0 + bcol;

    unsigned long long acc[4][8];
    #pragma unroll
    for (int i = 0; i < 4; i++)
        #pragma unroll
        for (int j = 0; j < 8; j++) acc[i][j] = 0ull;

    for (int kt = 0; kt < kLen; kt += BK) {
        float4 av  = *(const float4*)(Aptr);
        float4 bv0 = *(const float4*)(Bptr);
        float4 bv1 = *(const float4*)(Bptr + 64);
        As[akq + 0][arow] = av.x;
        As[akq + 1][arow] = av.y;
        As[akq + 2][arow] = av.z;
        As[akq + 3][arow] = av.w;
        *(float4*)&Bs[brow][bcol]      = bv0;
        *(float4*)&Bs[brow][bcol + 64] = bv1;
        __syncthreads();

        #pragma unroll
        for (int k = 0; k < BK; k++) {
            float4 a0 = *(const float4*)&As[k][ty * 8];
            float4 a1 = *(const float4*)&As[k][ty * 8 + 4];
            float4 c0 = *(const float4*)&Bs[k][tx * 8];
            float4 c1 = *(const float4*)&Bs[k][tx * 8 + 4];
            unsigned long long a2[4];
            a2[0] = pk2(a0.x, a0.y);
            a2[1] = pk2(a0.z, a0.w);
            a2[2] = pk2(a1.x, a1.y);
            a2[3] = pk2(a1.z, a1.w);
            float bv[8] = {c0.x, c0.y, c0.z, c0.w, c1.x, c1.y, c1.z, c1.w};
            #pragma unroll
            for (int j = 0; j < 8; j++) {
                unsigned long long b2 = pk2(bv[j], bv[j]);
                #pragma unroll
                for (int i = 0; i < 4; i++)
                    acc[i][j] = fma2(a2[i], b2, acc[i][j]);
            }
        }
        __syncthreads();
        Aptr += BK;
        Bptr += (size_t)BK * N;
    }

    const int nbase = n0 + tx * 8;
    #pragma unroll
    for (int i = 0; i < 4; i++) {
        float r0[8], r1[8];
        #pragma unroll
        for (int j = 0; j < 8; j++) unpk2(acc[i][j], r0[j], r1[j]);
        if (EPI == EPBR) {
            #pragma unroll
            for (int j = 0; j < 8; j++) {
                float bb = bias[nbase + j];
                r0[j] = fmaxf(r0[j] + bb, 0.f);
                r1[j] = fmaxf(r1[j] + bb, 0.f);
            }
        }
        const int m = m0 + ty * 8 + 2 * i;
        float4* p0 = (float4*)(Cg + (size_t)m * N + nbase);
        float4* p1 = (float4*)(Cg + (size_t)(m + 1) * N + nbase);
        p0[0] = make_float4(r0[0], r0[1], r0[2], r0[3]);
        p0[1] = make_float4(r0[4], r0[5], r0[6], r0[7]);
        p1[0] = make_float4(r1[0], r1[1], r1[2], r1[3]);
        p1[1] = make_float4(r1[4], r1[5], r1[6], r1[7]);
    }
}

// ---------------- reductions / epilogues ------------------------------------
__global__ void add4_kernel(float* __restrict__ a, int n4) {
    int i = blockIdx.x * blockDim.x + threadIdx.x;
    if (i >= n4) return;
    const size_t st = (size_t)NN * D0 / 4;
    float4 x0 = ((const float4*)a)[i];
    float4 x1 = ((const float4*)a)[i + st];
    float4 x2 = ((const float4*)a)[i + 2 * st];
    float4 x3 = ((const float4*)a)[i + 3 * st];
    x0.x = (x0.x + x1.x) + (x2.x + x3.x);
    x0.y = (x0.y + x1.y) + (x2.y + x3.y);
    x0.z = (x0.z + x1.z) + (x2.z + x3.z);
    x0.w = (x0.w + x1.w) + (x2.w + x3.w);
    ((float4*)a)[i] = x0;
}

__global__ void add2_bias_relu_kernel(const float* __restrict__ a,
                                      const float* __restrict__ b,
                                      const float* __restrict__ bias,
                                      float* __restrict__ out, int n4) {
    int i = blockIdx.x * blockDim.x + threadIdx.x;
    if (i >= n4) return;
    float4 x = ((const float4*)a)[i];
    float4 y = ((const float4*)b)[i];
    int c = (i * 4) & (D2 - 1);
    x.x = fmaxf(x.x + y.x + bias[c + 0], 0.f);
    x.y = fmaxf(x.y + y.y + bias[c + 1], 0.f);
    x.z = fmaxf(x.z + y.z + bias[c + 2], 0.f);
    x.w = fmaxf(x.w + y.w + bias[c + 3], 0.f);
    ((float4*)out)[i] = x;
}

// ---------------- Q head ----------------------------------------------------
__global__ void qhead_kernel(const float* __restrict__ S,
                             const float* __restrict__ Wq2,
                             const float* __restrict__ bq2,
                             float* __restrict__ q, int rows) {
    int gw   = (blockIdx.x * blockDim.x + threadIdx.x) >> 5;
    int lane = threadIdx.x & 31;
    if (gw >= rows) return;
    const float* row = S + (size_t)gw * QH;
    float sum = 0.f;
    #pragma unroll
    for (int i = 0; i < QH / 32; i++)
        sum = fmaf(row[lane + 32 * i], Wq2[lane + 32 * i], sum);
    #pragma unroll
    for (int o = 16; o > 0; o >>= 1) sum += __shfl_xor_sync(0xFFFFFFFFu, sum, o);
    if (lane == 0) q[gw] = sum + bq2[0];
}

// ---------------------------------------------------------------------------
extern "C" void kernel_launch(void* const* d_in, const int* in_sizes, int n_in,
                              void* d_out, int out_size) {
    const float* state = (const float*)d_in[0];
    const float* A     = (const float*)d_in[1];
    const float* gamma = (const float*)d_in[2];
    const float* beta  = (const float*)d_in[3];
    const float* W1    = (const float*)d_in[4];
    const float* b1    = (const float*)d_in[5];
    const float* W2    = (const float*)d_in[6];
    const float* b2    = (const float*)d_in[7];
    const float* Wq1   = (const float*)d_in[8];
    const float* bq1   = (const float*)d_in[9];
    const float* Wq2   = (const float*)d_in[10];
    const float* bq2   = (const float*)d_in[11];
    float* q = (float*)d_out;

    unsigned short *Ahi, *Alo, *Xt, *Pt;
    float *G1, *H1, *P2, *G2, *S;
    cudaGetSymbolAddress((void**)&Ahi, g_Ahi);
    cudaGetSymbolAddress((void**)&Alo, g_Alo);
    cudaGetSymbolAddress((void**)&Xt,  g_Xt);
    cudaGetSymbolAddress((void**)&Pt,  g_Pt);
    cudaGetSymbolAddress((void**)&G1,  g_G1);
    cudaGetSymbolAddress((void**)&H1,  g_H1);
    cudaGetSymbolAddress((void**)&P2,  g_P2);
    cudaGetSymbolAddress((void**)&G2,  g_G2);
    cudaGetSymbolAddress((void**)&S,   g_S);

    // 2-stage pipeline: 2 * 96 KB = 192 KB dynamic smem
    constexpr int SMEM_HMMA = 2 * STAGE_BYTES;
    cudaFuncSetAttribute(hmma_gemm_kernel,
                         cudaFuncAttributeMaxDynamicSharedMemorySize, SMEM_HMMA);

    // 1) BN stats, then normalize + tiled transpose + bf16-split X
    bn_stats_kernel<<<D0, 256>>>(state, NN, D0);
    bn_apply_tsplit_kernel<<<dim3(D0 / 32, NN / 32), dim3(32, 8)>>>(state, gamma,
                                                                    beta, Xt);

    // 2) split A into bf16 hi/lo
    splitA_kernel<<<(NN * NN / 4 + 255) / 256, 256>>>(A, Ahi, Alo, NN * NN / 4);

    // 3) G1 = A @ X  (HMMA 3-pass, 256x128 tiles, split-K=4 -> 128 CTAs)
    hmma_gemm_kernel<<<dim3(1, NN / 256, 4), 256, SMEM_HMMA>>>(Ahi, Alo, Xt, G1,
                                                               D0, NN / 4);
    add4_kernel<<<(NN * D0 / 4 + 255) / 256, 256>>>(G1, NN * D0 / 4);

    // 4) H1 = relu(G1 @ W1 + b1)
    sgemm64_kernel<EPBR><<<dim3(D1 / 128, NN / 64, 1), 128>>>(G1, W1, H1, b1,
                                                              NN, D1, D0, D0);

    // 5) P2 = H1 @ W2, then tiled transpose + split
    sgemm64_kernel<EPN><<<dim3(D2 / 128, NN / 64, 1), 128>>>(H1, W2, P2, nullptr,
                                                             NN, D2, D1, D1);
    tsplit_p2_kernel<<<dim3(D2 / 32, NN / 32), dim3(32, 8)>>>(P2, Pt);

    // 6) G2 = A @ P2  (HMMA 3-pass, 2 n-tiles x split-K=2 -> 128 CTAs)
    hmma_gemm_kernel<<<dim3(2, NN / 256, 2), 256, SMEM_HMMA>>>(Ahi, Alo, Pt, G2,
                                                               D2, NN / 2);
    add2_bias_relu_kernel<<<(NN * D2 / 4 + 255) / 256, 256>>>(G2, G2 + (size_t)NN * D2,
                                                              b2, H1, NN * D2 / 4);
    // H1 now holds H2

    // 7) S = relu(H2 @ Wq1 + bq1)
    sgemm64_kernel<EPBR><<<dim3(QH / 128, NN / 64, 1), 128>>>(H1, Wq1, S, bq1,
                                                              NN, QH, D2, D2);

    // 8) q = S @ Wq2 + bq2
    qhead_kernel<<<(NN * 32 + 255) / 256, 256>>>(S, Wq2, bq2, q, NN);

    (void)in_sizes; (void)n_in; (void)out_size;
}